// round 6
// baseline (speedup 1.0000x reference)
#include <cuda_runtime.h>
#include <cstdint>

// SVD predict: TMA row-gather (cp.async.bulk 256B/row) -> smem -> bulk store.
// Bypasses the per-SM L1tex wavefront queue that capped LDG-based variants.
//
// Inputs (metadata order):
//   d_in[0] user_item  int32  [131072, 2]
//   d_in[1] pu         f32    [1000000, 64]
//   d_in[2] qi         f32    [500000, 64]
//   d_in[3] bu         f32    [1000000]
//   d_in[4] bi         f32    [500000]
//   d_in[5] global_mean f32   [1]
// Output: float32 [131072 predict] ++ [131072 x 128 features]

#define BATCH        131072
#define THREADS      128
#define ROWS_PER_CTA 32
#define ROW_FLOATS   128                         // [p(64) | q(64)]
#define ROW_BYTES    256                         // one table row
#define TILE_BYTES   (ROWS_PER_CTA * ROW_FLOATS * 4)   // 16 KB

__device__ __forceinline__ uint32_t smem_u32(const void* p) {
    uint32_t a;
    asm("{ .reg .u64 t; cvta.to.shared.u64 t, %1; cvt.u32.u64 %0, t; }"
        : "=r"(a) : "l"(p));
    return a;
}

__global__ __launch_bounds__(THREADS)
void svd_predict_kernel(const int2* __restrict__ ui,
                        const float* __restrict__ pu,
                        const float* __restrict__ qi,
                        const float* __restrict__ bu,
                        const float* __restrict__ bi,
                        const float* __restrict__ gm,
                        float* __restrict__ out_pred,
                        float* __restrict__ out_feat)     // [BATCH][128]
{
    __shared__ __align__(128) float tile[ROWS_PER_CTA * ROW_FLOATS];  // 16 KB
    __shared__ __align__(8) uint64_t mbar;
    __shared__ int2 ids_s[ROWS_PER_CTA];

    const int t  = threadIdx.x;
    const int r0 = blockIdx.x * ROWS_PER_CTA;
    const uint32_t s_tile = smem_u32(tile);
    const uint32_t s_mbar = smem_u32(&mbar);

    // ---- init: mbarrier + ids ----
    if (t == 0) {
        asm volatile("mbarrier.init.shared.b64 [%0], 1;" :: "r"(s_mbar) : "memory");
        asm volatile("mbarrier.arrive.expect_tx.shared.b64 _, [%0], %1;"
                     :: "r"(s_mbar), "r"((uint32_t)(2 * ROWS_PER_CTA * ROW_BYTES))
                     : "memory");
    }
    if (t < ROWS_PER_CTA) ids_s[t] = __ldg(&ui[r0 + t]);
    __syncthreads();

    // ---- TMA gathers: 64 bulk copies of 256B (one per table row) ----
    // thread t<64: row = t>>1, half 0 = p, half 1 = q.
    if (t < 2 * ROWS_PER_CTA) {
        const int row  = t >> 1;
        const int half = t & 1;
        const int2 ids = ids_s[row];
        const float* src = half ? (qi + (size_t)ids.y * 64)
                                : (pu + (size_t)ids.x * 64);
        const uint32_t dst = s_tile + (uint32_t)(row * 512 + half * ROW_BYTES);
        asm volatile(
            "cp.async.bulk.shared::cta.global.mbarrier::complete_tx::bytes "
            "[%0], [%1], %2, [%3];"
            :: "r"(dst), "l"(src), "r"((uint32_t)ROW_BYTES), "r"(s_mbar)
            : "memory");
    }

    // ---- wait for all 16 KB to land (HW sleep, parity 0) ----
    {
        uint32_t done;
        asm volatile(
            "{\n\t.reg .pred p;\n\t"
            "mbarrier.try_wait.parity.acquire.cta.shared::cta.b64 p, [%1], 0;\n\t"
            "selp.b32 %0, 1, 0, p;\n\t}"
            : "=r"(done) : "r"(s_mbar) : "memory");
        if (!done) {
            asm volatile(
                "{\n\t.reg .pred P1;\n\t"
                "WL_%=:\n\t"
                "mbarrier.try_wait.parity.acquire.cta.shared::cta.b64 P1, [%0], 0, 0x989680;\n\t"
                "@P1 bra.uni WD_%=;\n\t"
                "bra.uni WL_%=;\n\t"
                "WD_%=:\n\t}"
                :: "r"(s_mbar) : "memory");
        }
    }

    // ---- dots: warp w handles rows w*8 .. w*8+7 ----
    const int warp = t >> 5;
    const int lane = t & 31;
    float myd = 0.0f;                     // lane k<8 holds dot of row warp*8+k

    #pragma unroll
    for (int k = 0; k < 8; k++) {
        const int row = warp * 8 + k;
        const float2* r2 = reinterpret_cast<const float2*>(tile + row * ROW_FLOATS);
        const float2 p = r2[lane];
        const float2 q = r2[lane + 32];
        float d = p.x * q.x + p.y * q.y;
        #pragma unroll
        for (int off = 16; off; off >>= 1)
            d += __shfl_xor_sync(0xFFFFFFFFu, d, off);
        if (lane == k) myd = d;
    }

    // ---- predictions: lanes 0..7 of each warp, parallel bias gathers ----
    if (lane < 8) {
        const int row = warp * 8 + lane;
        const int2 ids = ids_s[row];
        float pr = __ldg(gm) + __ldg(&bu[ids.x]) + __ldg(&bi[ids.y]) + myd;
        out_pred[r0 + row] = fminf(fmaxf(pr, 1.0f), 5.0f);
    }

    // ---- feature store: one 16 KB bulk copy, smem -> contiguous rows ----
    __syncthreads();
    if (t == 0) {
        float* dst = out_feat + (size_t)r0 * ROW_FLOATS;
        asm volatile("cp.async.bulk.global.shared::cta.bulk_group [%0], [%1], %2;"
                     :: "l"(dst), "r"(s_tile), "r"((uint32_t)TILE_BYTES)
                     : "memory");
        asm volatile("cp.async.bulk.commit_group;\n"
                     "cp.async.bulk.wait_group.read 0;\n" ::: "memory");
    }
}

extern "C" void kernel_launch(void* const* d_in, const int* in_sizes, int n_in,
                              void* d_out, int out_size)
{
    const int2*  ui = (const int2*) d_in[0];
    const float* pu = (const float*)d_in[1];
    const float* qi = (const float*)d_in[2];
    const float* bu = (const float*)d_in[3];
    const float* bi = (const float*)d_in[4];
    const float* gm = (const float*)d_in[5];

    float* out_pred = (float*)d_out;               // [BATCH]
    float* out_feat = out_pred + BATCH;            // [BATCH][128]

    const int blocks = BATCH / ROWS_PER_CTA;       // 4096
    svd_predict_kernel<<<blocks, THREADS>>>(ui, pu, qi, bu, bi, gm,
                                            out_pred, out_feat);
}

// round 8
// speedup vs baseline: 1.0872x; 1.0872x over previous
#include <cuda_runtime.h>
#include <cstdint>

// SVD predict: persistent warps, double-buffered cp.async pipeline.
// Each warp loops over 8-row batches; batch i+1 loads while batch i computes.
//
// Inputs (metadata order):
//   d_in[0] user_item  int32  [131072, 2]
//   d_in[1] pu         f32    [1000000, 64]
//   d_in[2] qi         f32    [500000, 64]
//   d_in[3] bu         f32    [1000000]
//   d_in[4] bi         f32    [500000]
//   d_in[5] global_mean f32   [1]
// Output: float32 [131072 predict] ++ [131072 x 128 features]

#define BATCH_ROWS   131072
#define NB           16384           // batches of 8 rows
#define THREADS      128
#define WARPS_PER_CTA 4
#define GRID         888             // 6 CTAs x 148 SMs, one wave
#define STRIDE       (GRID * WARPS_PER_CTA)   // 3552 warps
#define ROW_FLOATS   128             // [p(64) | q(64)]
#define BATCH_FLOATS (8 * ROW_FLOATS)         // 1024 floats = 4 KB
#define BATCH_BYTES  4096

__device__ __forceinline__ uint32_t smem_u32(const void* p) {
    uint32_t a;
    asm("{ .reg .u64 t; cvta.to.shared.u64 t, %1; cvt.u32.u64 %0, t; }"
        : "=r"(a) : "l"(p));
    return a;
}

struct BInfo { int2 ids; float bu, bi; };

__device__ __forceinline__ BInfo load_binfo(int b, int lane,
                                            const int2* __restrict__ ui,
                                            const float* __restrict__ bu,
                                            const float* __restrict__ bi) {
    BInfo r; r.ids = make_int2(0, 0); r.bu = 0.f; r.bi = 0.f;
    if (b < NB && lane < 8) {
        r.ids = __ldg(&ui[b * 8 + lane]);
        r.bu  = __ldg(&bu[r.ids.x]);
        r.bi  = __ldg(&bi[r.ids.y]);
    }
    return r;
}

__device__ __forceinline__ void prefetch_batch(float* wbuf, int sel, int lane,
                                               const BInfo& bi_,
                                               const float4* __restrict__ pu4,
                                               const float4* __restrict__ qi4) {
    #pragma unroll
    for (int k = 0; k < 8; k++) {
        const int uid = __shfl_sync(0xFFFFFFFFu, bi_.ids.x, k);
        const int iid = __shfl_sync(0xFFFFFFFFu, bi_.ids.y, k);
        const float4* src = (lane < 16)
            ? pu4 + (size_t)uid * 16 + lane
            : qi4 + (size_t)iid * 16 + (lane - 16);
        const uint32_t dst =
            smem_u32(wbuf + sel * BATCH_FLOATS + k * ROW_FLOATS + lane * 4);
        asm volatile("cp.async.cg.shared.global [%0], [%1], 16;\n"
                     :: "r"(dst), "l"(src));
    }
    asm volatile("cp.async.commit_group;\n" ::: "memory");
}

__global__ __launch_bounds__(THREADS)
void svd_predict_kernel(const int2* __restrict__ ui,
                        const float4* __restrict__ pu4,
                        const float4* __restrict__ qi4,
                        const float* __restrict__ bu,
                        const float* __restrict__ bi,
                        const float* __restrict__ gm,
                        float* __restrict__ out_pred,
                        float* __restrict__ out_feat)
{
    __shared__ __align__(128) float buf[WARPS_PER_CTA][2][BATCH_FLOATS]; // 32 KB

    const int warp = threadIdx.x >> 5;
    const int lane = threadIdx.x & 31;
    float* const wbuf = &buf[warp][0][0];
    const float gmv = __ldg(gm);

    int b  = blockIdx.x * WARPS_PER_CTA + warp;   // < 3552 < NB always
    int bn = b + STRIDE;

    BInfo cur = load_binfo(b,  lane, ui, bu, bi);
    BInfo nxt = load_binfo(bn, lane, ui, bu, bi);

    int sel = 0;
    prefetch_batch(wbuf, sel, lane, cur, pu4, qi4);

    while (true) {
        const int  b2   = bn + STRIDE;
        const bool more = (bn < NB);
        BInfo nxt2 = load_binfo(b2, lane, ui, bu, bi);

        if (more) {
            // buffer sel^1 must be free of the pending bulk-store's smem reads
            if (lane == 0)
                asm volatile("cp.async.bulk.wait_group.read 0;\n" ::: "memory");
            __syncwarp();
            prefetch_batch(wbuf, sel ^ 1, lane, nxt, pu4, qi4);
            asm volatile("cp.async.wait_group 1;\n" ::: "memory");
        } else {
            asm volatile("cp.async.wait_group 0;\n" ::: "memory");
        }
        __syncwarp();

        // ---- compute 8 rows of batch b from buffer sel ----
        float myd = 0.0f;                  // lane k<8 holds dot of row k
        #pragma unroll
        for (int k = 0; k < 8; k++) {
            const float2* r2 = reinterpret_cast<const float2*>(
                wbuf + sel * BATCH_FLOATS + k * ROW_FLOATS);
            const float2 p = r2[lane];
            const float2 q = r2[lane + 32];
            float d = p.x * q.x + p.y * q.y;
            #pragma unroll
            for (int off = 16; off; off >>= 1)
                d += __shfl_xor_sync(0xFFFFFFFFu, d, off);
            if (lane == k) myd = d;
        }

        if (lane < 8) {
            float pr = gmv + cur.bu + cur.bi + myd;
            out_pred[b * 8 + lane] = fminf(fmaxf(pr, 1.0f), 5.0f);
        }

        // ---- feature bulk store: 4 KB contiguous ----
        asm volatile("fence.proxy.async.shared::cta;\n" ::: "memory");
        __syncwarp();
        if (lane == 0) {
            float* dst = out_feat + (size_t)b * 8 * ROW_FLOATS;
            asm volatile(
                "cp.async.bulk.global.shared::cta.bulk_group [%0], [%1], %2;\n"
                :: "l"(dst), "r"(smem_u32(wbuf + sel * BATCH_FLOATS)),
                   "r"((uint32_t)BATCH_BYTES) : "memory");
            asm volatile("cp.async.bulk.commit_group;\n" ::: "memory");
        }

        if (!more) break;
        b = bn; bn = b2; cur = nxt; nxt = nxt2; sel ^= 1;
    }

    if (lane == 0)
        asm volatile("cp.async.bulk.wait_group.read 0;\n" ::: "memory");
}

extern "C" void kernel_launch(void* const* d_in, const int* in_sizes, int n_in,
                              void* d_out, int out_size)
{
    const int2*   ui  = (const int2*)  d_in[0];
    const float4* pu4 = (const float4*)d_in[1];
    const float4* qi4 = (const float4*)d_in[2];
    const float*  bu  = (const float*) d_in[3];
    const float*  bi  = (const float*) d_in[4];
    const float*  gm  = (const float*) d_in[5];

    float* out_pred = (float*)d_out;               // [BATCH_ROWS]
    float* out_feat = out_pred + BATCH_ROWS;       // [BATCH_ROWS][128]

    svd_predict_kernel<<<GRID, THREADS>>>(ui, pu4, qi4, bu, bi, gm,
                                          out_pred, out_feat);
}

// round 11
// speedup vs baseline: 1.2947x; 1.1908x over previous
#include <cuda_runtime.h>
#include <cstdint>

// SVD predict, 4 rows per warp (R2 structure) + L2-residency cache steering
// via createpolicy/cache_hint (direct .L2::evict_last modifier is v8-only on
// sm_103a ptxas):
//   - table gathers:  ld.global.nc.L2::cache_hint (evict_last policy)
//   - feature stores: st.global.cs (streaming; don't evict the tables)
//
// Inputs (metadata order):
//   d_in[0] user_item  int32  [131072, 2]
//   d_in[1] pu         f32    [1000000, 64]
//   d_in[2] qi         f32    [500000, 64]
//   d_in[3] bu         f32    [1000000]
//   d_in[4] bi         f32    [500000]
//   d_in[5] global_mean f32   [1]
// Output: float32 [131072 predict] ++ [131072 x 128 features]

#define BATCH 131072
#define ROWS_PER_WARP 4

__device__ __forceinline__ uint64_t mk_evict_last_policy() {
    uint64_t pol;
    asm("createpolicy.fractional.L2::evict_last.b64 %0, 1.0;" : "=l"(pol));
    return pol;
}

__device__ __forceinline__ float4 ld_evl4(const float4* p, uint64_t pol) {
    float4 v;
    asm("ld.global.nc.L2::cache_hint.v4.f32 {%0,%1,%2,%3}, [%4], %5;"
        : "=f"(v.x), "=f"(v.y), "=f"(v.z), "=f"(v.w) : "l"(p), "l"(pol));
    return v;
}

__device__ __forceinline__ float ld_evl(const float* p, uint64_t pol) {
    float v;
    asm("ld.global.nc.L2::cache_hint.f32 %0, [%1], %2;"
        : "=f"(v) : "l"(p), "l"(pol));
    return v;
}

__global__ __launch_bounds__(256)
void svd_predict_kernel(const int2* __restrict__ ui,
                        const float4* __restrict__ pu4,   // [N_USERS][16]
                        const float4* __restrict__ qi4,   // [N_ITEMS][16]
                        const float* __restrict__ bu,
                        const float* __restrict__ bi,
                        const float* __restrict__ gm,
                        float* __restrict__ out_pred,
                        float4* __restrict__ out_feat4)   // [BATCH][32]
{
    const int warp = (blockIdx.x * blockDim.x + threadIdx.x) >> 5;
    const int lane = threadIdx.x & 31;
    const int half = lane >> 4;      // 0 or 1
    const int g    = lane & 15;      // lane within half-warp

    const uint64_t pol = mk_evict_last_policy();

    const int r0 = warp * ROWS_PER_WARP + half * 2;
    const int r1 = r0 + 1;

    const int2 id0 = __ldg(&ui[r0]);
    const int2 id1 = __ldg(&ui[r1]);

    // 4 independent 16B gathers per thread, pinned toward L2 residency.
    const float4 a0 = ld_evl4(pu4 + (size_t)id0.x * 16 + g, pol);
    const float4 b0 = ld_evl4(qi4 + (size_t)id0.y * 16 + g, pol);
    const float4 a1 = ld_evl4(pu4 + (size_t)id1.x * 16 + g, pol);
    const float4 b1 = ld_evl4(qi4 + (size_t)id1.y * 16 + g, pol);

    float d0 = a0.x * b0.x + a0.y * b0.y + a0.z * b0.z + a0.w * b0.w;
    float d1 = a1.x * b1.x + a1.y * b1.y + a1.z * b1.z + a1.w * b1.w;

    #pragma unroll
    for (int off = 8; off; off >>= 1) {
        d0 += __shfl_xor_sync(0xFFFFFFFFu, d0, off);
        d1 += __shfl_xor_sync(0xFFFFFFFFu, d1, off);
    }

    // Streaming feature stores: [p | q] per row, full 128B lines.
    float4* f0 = out_feat4 + (size_t)r0 * 32;
    float4* f1 = out_feat4 + (size_t)r1 * 32;
    __stcs(f0 + g,      a0);
    __stcs(f0 + g + 16, b0);
    __stcs(f1 + g,      a1);
    __stcs(f1 + g + 16, b1);

    if (g == 0) {
        const float base = __ldg(gm);
        float p0 = base + ld_evl(&bu[id0.x], pol) + ld_evl(&bi[id0.y], pol) + d0;
        float p1 = base + ld_evl(&bu[id1.x], pol) + ld_evl(&bi[id1.y], pol) + d1;
        out_pred[r0] = fminf(fmaxf(p0, 1.0f), 5.0f);
        out_pred[r1] = fminf(fmaxf(p1, 1.0f), 5.0f);
    }
}

extern "C" void kernel_launch(void* const* d_in, const int* in_sizes, int n_in,
                              void* d_out, int out_size)
{
    const int2*   ui  = (const int2*)  d_in[0];
    const float4* pu4 = (const float4*)d_in[1];
    const float4* qi4 = (const float4*)d_in[2];
    const float*  bu  = (const float*) d_in[3];
    const float*  bi  = (const float*) d_in[4];
    const float*  gm  = (const float*) d_in[5];

    float*  out_pred  = (float*)d_out;                 // [BATCH]
    float4* out_feat4 = (float4*)(out_pred + BATCH);   // [BATCH][32] float4

    const int threads = 256;                                  // 8 warps
    const int warps   = BATCH / ROWS_PER_WARP;                // 32768
    const int blocks  = warps / (threads / 32);               // 4096
    svd_predict_kernel<<<blocks, threads>>>(ui, pu4, qi4, bu, bi, gm,
                                            out_pred, out_feat4);
}